// round 3
// baseline (speedup 1.0000x reference)
#include <cuda_runtime.h>
#include <cuda_bf16.h>

#define N_NODES 50000
#define N_EDGES 800000
#define D_IN    128
#define HF      64    // H*F
#define H       4
#define F       16

// Scratch (no allocation allowed): ft 12.8MB, ex 12.8MB, denom 0.8MB
__device__ float g_ft[N_NODES * HF];
__device__ float g_ex[N_EDGES * H];
__device__ float g_denom[N_NODES * H];

// ---------------------------------------------------------------------------
// K0: zero d_out (poisoned by harness) and the softmax denominators
// ---------------------------------------------------------------------------
__global__ void k_zero(float* __restrict__ out) {
    int i = blockIdx.x * blockDim.x + threadIdx.x;
    if (i < N_NODES * HF) out[i] = 0.f;
    if (i < N_NODES * H)  g_denom[i] = 0.f;
}

// ---------------------------------------------------------------------------
// K1: ft = feat @ W   ([N,128] @ [128,64])
// Block: 256 threads, 16 nodes per block (50000 = 3125 * 16, exact).
// W held transposed+padded in shared so the k-loop is float4 on both operands.
// ---------------------------------------------------------------------------
__global__ __launch_bounds__(256) void k_gemm(const float* __restrict__ feat,
                                              const float* __restrict__ W) {
    __shared__ float sWt[HF][132];          // [col][k], pad 132 kills bank conflicts
    __shared__ float sfeat[16 * D_IN];      // 16 node rows

    int tid = threadIdx.x;

    // Load W transposed: W is [k][c] row-major (128x64)
    for (int idx = tid; idx < D_IN * HF; idx += 256) {
        int k = idx >> 6;
        int c = idx & 63;
        sWt[c][k] = W[idx];
    }

    int node0 = blockIdx.x * 16;
    const float4* fv = (const float4*)(feat + (size_t)node0 * D_IN);
    float4* sv = (float4*)sfeat;
    for (int idx = tid; idx < 16 * D_IN / 4; idx += 256)
        sv[idx] = fv[idx];
    __syncthreads();

    int c  = tid & 63;    // output column
    int r0 = tid >> 6;    // 0..3
    const float4* wt4 = (const float4*)&sWt[c][0];   // row start is 528B -> 16B aligned

    #pragma unroll
    for (int rr = 0; rr < 4; rr++) {
        int n = r0 * 4 + rr;
        const float4* f4 = (const float4*)&sfeat[n * D_IN];
        float acc = 0.f;
        #pragma unroll
        for (int k4 = 0; k4 < D_IN / 4; k4++) {
            float4 a = f4[k4];
            float4 w = wt4[k4];
            acc += a.x * w.x + a.y * w.y + a.z * w.z + a.w * w.w;
        }
        g_ft[(size_t)(node0 + n) * HF + c] = acc;   // coalesced: consecutive tid -> consecutive c
    }
}

// ---------------------------------------------------------------------------
// K2: per-edge attention scores -> exp -> denom accumulation.
// 16 threads per edge; thread j handles float4 #j of the 64-float rows.
// Head h = j/4; intra-head reduce via shfl_xor(1), shfl_xor(2).
// Softmax max-subtraction skipped (shift-invariant; scores ~N(0,1), no overflow).
// ---------------------------------------------------------------------------
__global__ __launch_bounds__(256) void k_score(const int* __restrict__ src,
                                               const int* __restrict__ dst) {
    int gtid = blockIdx.x * 256 + threadIdx.x;
    int edge = gtid >> 4;
    int j    = gtid & 15;

    int s = src[edge];
    int d = dst[edge];

    const float4* ftv = (const float4*)g_ft;
    float4 a = ftv[(size_t)s * 16 + j];
    float4 b = ftv[(size_t)d * 16 + j];
    float p = a.x * b.x + a.y * b.y + a.z * b.z + a.w * b.w;

    // reduce within the 4-lane head group
    p += __shfl_xor_sync(0xffffffffu, p, 1);
    p += __shfl_xor_sync(0xffffffffu, p, 2);

    if ((j & 3) == 0) {
        int   h  = j >> 2;
        float ex = __expf(p * 0.25f);   // * 1/sqrt(F), F=16
        g_ex[(size_t)edge * 4 + h] = ex;
        atomicAdd(&g_denom[(size_t)d * 4 + h], ex);
    }
}

// ---------------------------------------------------------------------------
// K3: weighted scatter of source features into destination nodes.
// 16 threads per edge; each thread: one float4 message, one RED.v4 (4x fewer
// atomic ops than scalar atomicAdd).
// ---------------------------------------------------------------------------
__global__ __launch_bounds__(256) void k_scatter(const int* __restrict__ src,
                                                 const int* __restrict__ dst,
                                                 float* __restrict__ out) {
    int gtid = blockIdx.x * 256 + threadIdx.x;
    int edge = gtid >> 4;
    int j    = gtid & 15;

    int s = src[edge];
    int d = dst[edge];
    int h = j >> 2;

    float sa = g_ex[(size_t)edge * 4 + h] / g_denom[(size_t)d * 4 + h];

    const float4* ftv = (const float4*)g_ft;
    float4 a = ftv[(size_t)s * 16 + j];

    float* addr = out + (size_t)d * 64 + j * 4;   // 16B aligned (d*256B + j*16B)
    asm volatile("red.global.add.v4.f32 [%0], {%1,%2,%3,%4};"
                 :: "l"(addr), "f"(a.x * sa), "f"(a.y * sa),
                    "f"(a.z * sa), "f"(a.w * sa)
                 : "memory");
}

// ---------------------------------------------------------------------------
extern "C" void kernel_launch(void* const* d_in, const int* in_sizes, int n_in,
                              void* d_out, int out_size) {
    const float* feat = (const float*)d_in[0];
    const float* W    = (const float*)d_in[1];
    const int*   src  = (const int*)d_in[2];
    const int*   dst  = (const int*)d_in[3];
    float* out = (float*)d_out;

    k_zero<<<(N_NODES * HF + 255) / 256, 256>>>(out);
    k_gemm<<<N_NODES / 16, 256>>>(feat, W);
    k_score<<<N_EDGES * 16 / 256, 256>>>(src, dst);
    k_scatter<<<N_EDGES * 16 / 256, 256>>>(src, dst, out);
}

// round 4
// speedup vs baseline: 1.3611x; 1.3611x over previous
#include <cuda_runtime.h>
#include <cuda_bf16.h>

#define N_NODES 50000
#define N_EDGES 800000
#define D_IN    128
#define HF      64
#define H       4
#define F       16
#define NB      196   // ceil(50000/256)

// Static scratch (allocation is forbidden)
__device__ float g_ft[N_NODES * HF];        // projected features [N,64]
__device__ int   g_count[N_NODES];          // in-degree histogram
__device__ int   g_off[N_NODES + 1];        // CSR offsets (exclusive scan)
__device__ int   g_cursor[N_NODES];         // placement cursors
__device__ int   g_srcs[N_EDGES];           // src ids grouped by dst
__device__ int   g_bsum[NB];                // scan block sums
__device__ int   g_bbase[NB];               // scan block bases

// ---------------------------------------------------------------------------
__global__ void k_zero_count() {
    int i = blockIdx.x * 256 + threadIdx.x;
    if (i < N_NODES) g_count[i] = 0;
}

// ---------------------------------------------------------------------------
// K1: ft = feat @ W   ([N,128] @ [128,64]); 16 nodes / 256-thread block
// ---------------------------------------------------------------------------
__global__ __launch_bounds__(256) void k_gemm(const float* __restrict__ feat,
                                              const float* __restrict__ W) {
    __shared__ float sWt[HF][132];      // W transposed, padded
    __shared__ float sfeat[16 * D_IN];

    int tid = threadIdx.x;
    for (int idx = tid; idx < D_IN * HF; idx += 256) {
        int k = idx >> 6, c = idx & 63;
        sWt[c][k] = W[idx];
    }
    int node0 = blockIdx.x * 16;
    const float4* fv = (const float4*)(feat + (size_t)node0 * D_IN);
    float4* sv = (float4*)sfeat;
    for (int idx = tid; idx < 16 * D_IN / 4; idx += 256) sv[idx] = fv[idx];
    __syncthreads();

    int c  = tid & 63;
    int r0 = tid >> 6;
    const float4* wt4 = (const float4*)&sWt[c][0];
    #pragma unroll
    for (int rr = 0; rr < 4; rr++) {
        int n = r0 * 4 + rr;
        const float4* f4 = (const float4*)&sfeat[n * D_IN];
        float acc = 0.f;
        #pragma unroll
        for (int k4 = 0; k4 < D_IN / 4; k4++) {
            float4 a = f4[k4], w = wt4[k4];
            acc += a.x * w.x + a.y * w.y + a.z * w.z + a.w * w.w;
        }
        g_ft[(size_t)(node0 + n) * HF + c] = acc;
    }
}

// ---------------------------------------------------------------------------
// CSR construction: histogram -> block scan -> top scan -> add -> place
// ---------------------------------------------------------------------------
__global__ void k_hist(const int* __restrict__ dst) {
    int e = blockIdx.x * 256 + threadIdx.x;
    if (e < N_EDGES) atomicAdd(&g_count[dst[e]], 1);
}

__device__ __forceinline__ int warp_incl_scan(int x, int lane) {
    #pragma unroll
    for (int d = 1; d < 32; d <<= 1) {
        int y = __shfl_up_sync(0xffffffffu, x, d);
        if (lane >= d) x += y;
    }
    return x;
}

__global__ __launch_bounds__(256) void k_scan_block() {
    int i = blockIdx.x * 256 + threadIdx.x;
    int v = (i < N_NODES) ? g_count[i] : 0;
    int lane = threadIdx.x & 31, w = threadIdx.x >> 5;
    int x = warp_incl_scan(v, lane);
    __shared__ int wsum[8];
    if (lane == 31) wsum[w] = x;
    __syncthreads();
    if (threadIdx.x < 8) {
        int s = wsum[threadIdx.x], t = s;
        #pragma unroll
        for (int d = 1; d < 8; d <<= 1) {
            int y = __shfl_up_sync(0xffu, t, d);
            if ((int)threadIdx.x >= d) t += y;
        }
        wsum[threadIdx.x] = t - s;          // exclusive base per warp
    }
    __syncthreads();
    int incl = x + wsum[w];
    if (i < N_NODES) g_off[i] = incl - v;   // exclusive within block
    if (threadIdx.x == 255) g_bsum[blockIdx.x] = incl;
}

__global__ __launch_bounds__(256) void k_scan_top() {
    int i = threadIdx.x;
    int v = (i < NB) ? g_bsum[i] : 0;
    int lane = i & 31, w = i >> 5;
    int x = warp_incl_scan(v, lane);
    __shared__ int wsum[8];
    if (lane == 31) wsum[w] = x;
    __syncthreads();
    if (i < 8) {
        int s = wsum[i], t = s;
        #pragma unroll
        for (int d = 1; d < 8; d <<= 1) {
            int y = __shfl_up_sync(0xffu, t, d);
            if (i >= d) t += y;
        }
        wsum[i] = t - s;
    }
    __syncthreads();
    if (i < NB) g_bbase[i] = x + wsum[w] - v;   // exclusive
}

__global__ void k_scan_add() {
    int i = blockIdx.x * 256 + threadIdx.x;
    if (i < N_NODES) {
        int o = g_off[i] + g_bbase[blockIdx.x];
        g_off[i] = o;
        g_cursor[i] = o;
    }
    if (i == 0) g_off[N_NODES] = N_EDGES;
}

__global__ void k_place(const int* __restrict__ src, const int* __restrict__ dst) {
    int e = blockIdx.x * 256 + threadIdx.x;
    if (e < N_EDGES) {
        int pos = atomicAdd(&g_cursor[dst[e]], 1);
        g_srcs[pos] = src[e];
    }
}

// ---------------------------------------------------------------------------
// K_agg: fused score + softmax + aggregate, node-parallel.
// 16 threads per node; thread j owns float4 #j of the 64-float row.
// out[d] = (sum_e exp(e_e) * ft[src_e]) / (sum_e exp(e_e))
// (softmax max-shift cancels exactly in the ratio; scores ~N(0,1) so no overflow)
// ---------------------------------------------------------------------------
__global__ __launch_bounds__(256) void k_agg(float* __restrict__ out) {
    int gtid = blockIdx.x * 256 + threadIdx.x;
    int node = gtid >> 4;
    int j    = gtid & 15;
    unsigned gmask = 0xFu << ((threadIdx.x & 31) & ~3);  // 4-lane head group

    const float4* ftv = (const float4*)g_ft;
    float4 b = ftv[(size_t)node * 16 + j];   // own (dst) feature chunk

    int k   = g_off[node];
    int end = g_off[node + 1];

    float4 acc = make_float4(0.f, 0.f, 0.f, 0.f);
    float den = 0.f;

    #pragma unroll 2
    for (; k < end; ++k) {
        int s = g_srcs[k];                               // broadcast across 16 lanes
        float4 a = ftv[(size_t)s * 16 + j];              // 256B coalesced gather
        float p = a.x * b.x + a.y * b.y + a.z * b.z + a.w * b.w;
        p += __shfl_xor_sync(gmask, p, 1);
        p += __shfl_xor_sync(gmask, p, 2);               // full head dot in all 4 lanes
        float ex = __expf(p * 0.25f);                    // * 1/sqrt(F)
        acc.x += ex * a.x; acc.y += ex * a.y;
        acc.z += ex * a.z; acc.w += ex * a.w;
        den += ex;
    }

    float inv = (den > 0.f) ? (1.f / den) : 0.f;         // isolated node -> zeros
    float4 r = make_float4(acc.x * inv, acc.y * inv, acc.z * inv, acc.w * inv);
    ((float4*)out)[(size_t)node * 16 + j] = r;
}

// ---------------------------------------------------------------------------
extern "C" void kernel_launch(void* const* d_in, const int* in_sizes, int n_in,
                              void* d_out, int out_size) {
    const float* feat = (const float*)d_in[0];
    const float* W    = (const float*)d_in[1];
    const int*   src  = (const int*)d_in[2];
    const int*   dst  = (const int*)d_in[3];
    float* out = (float*)d_out;

    k_zero_count<<<NB, 256>>>();
    k_gemm<<<N_NODES / 16, 256>>>(feat, W);
    k_hist<<<N_EDGES / 256, 256>>>(dst);
    k_scan_block<<<NB, 256>>>();
    k_scan_top<<<1, 256>>>();
    k_scan_add<<<NB, 256>>>();
    k_place<<<N_EDGES / 256, 256>>>(src, dst);
    k_agg<<<N_NODES * 16 / 256, 256>>>(out);
}

// round 7
// speedup vs baseline: 1.6732x; 1.2292x over previous
#include <cuda_runtime.h>
#include <cuda_bf16.h>

#define N_NODES 50000
#define N_EDGES 800000
#define D_IN    128
#define HF      64
#define H       4
#define F       16
#define NB      196   // ceil(50000/256)

// Static scratch (allocation is forbidden)
__device__ float g_ft[N_NODES * HF];     // projected features [N,64]
__device__ int   g_count[N_NODES];       // in-degree (zero-init; k_alloc re-zeroes)
__device__ int   g_off[N_NODES];         // segment start (atomic-allocated, arbitrary order)
__device__ int   g_cnt[N_NODES];         // segment length
__device__ int   g_cursor[N_NODES];      // placement cursors
__device__ int   g_srcs[N_EDGES];        // src ids grouped by dst
__device__ int   g_total;                // allocation cursor

// Packed fp32x2 FMA (Blackwell FFMA2, PTX-only): acc = a*b + acc on both lanes
#define FMA2(acc, a, b) \
    asm("fma.rn.f32x2 %0, %1, %2, %0;" : "+l"(acc) : "l"(a), "l"(b))

__device__ __forceinline__ float unpack_sum(unsigned long long v0,
                                            unsigned long long v1) {
    float a, b, c, d;
    asm("mov.b64 {%0,%1}, %2;" : "=f"(a), "=f"(b) : "l"(v0));
    asm("mov.b64 {%0,%1}, %2;" : "=f"(c), "=f"(d) : "l"(v1));
    return (a + b) + (c + d);
}

// ---------------------------------------------------------------------------
// K1: ft = feat @ W  ([N,128]@[128,64]), fused with dst histogram.
// Grid 3125 x 256 = exactly N_EDGES threads and 16 nodes/block.
// W loaded once per k-step and applied to 4 nodes; packed f32x2 accumulation.
// NOTE: one ulonglong2 = 4 floats, so the k-loop runs D_IN/4 = 32 iterations.
// ---------------------------------------------------------------------------
__global__ __launch_bounds__(256) void k_gemm(const float* __restrict__ feat,
                                              const float* __restrict__ W,
                                              const int* __restrict__ dst) {
    int gtid = blockIdx.x * 256 + threadIdx.x;
    if (blockIdx.x == 0 && threadIdx.x == 0) g_total = 0;
    atomicAdd(&g_count[dst[gtid]], 1);        // histogram, overlaps smem fill

    __shared__ float sWt[HF][132];            // W transposed, pad kills conflicts
    __shared__ float sfeat[16 * D_IN];

    int tid = threadIdx.x;
    for (int idx = tid; idx < D_IN * HF; idx += 256) {
        int k = idx >> 6, c = idx & 63;
        sWt[c][k] = W[idx];
    }
    int node0 = blockIdx.x * 16;
    const float4* fv = (const float4*)(feat + (size_t)node0 * D_IN);
    float4* sv = (float4*)sfeat;
    for (int idx = tid; idx < 16 * D_IN / 4; idx += 256) sv[idx] = fv[idx];
    __syncthreads();

    int c  = tid & 63;
    int r0 = tid >> 6;
    const ulonglong2* wt2 = (const ulonglong2*)&sWt[c][0];  // 528B rows, 16B aligned
    const ulonglong2* f2[4];
    #pragma unroll
    for (int rr = 0; rr < 4; rr++)
        f2[rr] = (const ulonglong2*)&sfeat[(r0 * 4 + rr) * D_IN];

    unsigned long long acc[4][2] = {};        // 0ull == packed {0.f,0.f}
    #pragma unroll
    for (int k = 0; k < D_IN / 4; k++) {      // 32 steps x 4 floats = full K=128
        ulonglong2 w = wt2[k];
        #pragma unroll
        for (int rr = 0; rr < 4; rr++) {
            ulonglong2 a = f2[rr][k];
            FMA2(acc[rr][0], a.x, w.x);
            FMA2(acc[rr][1], a.y, w.y);
        }
    }
    #pragma unroll
    for (int rr = 0; rr < 4; rr++)
        g_ft[(size_t)(node0 + r0 * 4 + rr) * HF + c] =
            unpack_sum(acc[rr][0], acc[rr][1]);
}

// ---------------------------------------------------------------------------
// K2: segment allocation via global atomic cursor (order-free CSR) and
// g_count re-zero for the next graph replay.
// ---------------------------------------------------------------------------
__global__ void k_alloc() {
    int i = blockIdx.x * 256 + threadIdx.x;
    if (i < N_NODES) {
        int cnt = g_count[i];
        g_count[i] = 0;                       // restore invariant for next call
        int off = atomicAdd(&g_total, cnt);
        g_off[i]    = off;
        g_cnt[i]    = cnt;
        g_cursor[i] = off;
    }
}

// ---------------------------------------------------------------------------
// K3: place src ids into per-dst segments
// ---------------------------------------------------------------------------
__global__ void k_place(const int* __restrict__ src, const int* __restrict__ dst) {
    int e = blockIdx.x * 256 + threadIdx.x;   // grid exact: 800000/256
    int pos = atomicAdd(&g_cursor[dst[e]], 1);
    g_srcs[pos] = src[e];
}

// ---------------------------------------------------------------------------
// K4: fused score + softmax + aggregate, node-parallel.
// 16 threads/node, thread j owns float4 #j. Indices prefetched 16-wide
// (coalesced), broadcast via shfl(width=16), gathers unrolled x4 for MLP.
// out[d] = (sum_e exp(e_e)*ft[src_e]) / sum_e exp(e_e)  (max-shift cancels)
// ---------------------------------------------------------------------------
__global__ __launch_bounds__(256) void k_agg(float* __restrict__ out) {
    int gtid = blockIdx.x * 256 + threadIdx.x;
    int node = gtid >> 4;
    int j    = gtid & 15;
    unsigned hmask = 0xFFFFu << (threadIdx.x & 16);   // this node's 16 lanes

    const float4* ftv = (const float4*)g_ft;
    float4 b = ftv[(size_t)node * 16 + j];
    int beg = g_off[node];
    int cnt = g_cnt[node];

    float4 acc = make_float4(0.f, 0.f, 0.f, 0.f);
    float den = 0.f;

#define EDGE(A) do {                                                  \
        float p = (A).x * b.x + (A).y * b.y + (A).z * b.z + (A).w * b.w; \
        p += __shfl_xor_sync(hmask, p, 1);                            \
        p += __shfl_xor_sync(hmask, p, 2);                            \
        float ex = __expf(p * 0.25f);                                 \
        acc.x += ex * (A).x; acc.y += ex * (A).y;                     \
        acc.z += ex * (A).z; acc.w += ex * (A).w;                     \
        den += ex;                                                    \
    } while (0)

    for (int k0 = 0; k0 < cnt; k0 += 16) {
        int rem = cnt - k0;
        int lim = rem < 16 ? rem : 16;
        int myidx = 0;
        if (j < lim) myidx = g_srcs[beg + k0 + j];    // coalesced 64B load

        int t = 0;
        for (; t + 4 <= lim; t += 4) {
            int s0 = __shfl_sync(hmask, myidx, t + 0, 16);
            int s1 = __shfl_sync(hmask, myidx, t + 1, 16);
            int s2 = __shfl_sync(hmask, myidx, t + 2, 16);
            int s3 = __shfl_sync(hmask, myidx, t + 3, 16);
            float4 a0 = ftv[(size_t)s0 * 16 + j];     // 4 independent gathers
            float4 a1 = ftv[(size_t)s1 * 16 + j];
            float4 a2 = ftv[(size_t)s2 * 16 + j];
            float4 a3 = ftv[(size_t)s3 * 16 + j];
            EDGE(a0); EDGE(a1); EDGE(a2); EDGE(a3);
        }
        for (; t < lim; ++t) {
            int s = __shfl_sync(hmask, myidx, t, 16);
            float4 a = ftv[(size_t)s * 16 + j];
            EDGE(a);
        }
    }
#undef EDGE

    float inv = (den > 0.f) ? (1.f / den) : 0.f;      // isolated node -> zeros
    ((float4*)out)[(size_t)node * 16 + j] =
        make_float4(acc.x * inv, acc.y * inv, acc.z * inv, acc.w * inv);
}

// ---------------------------------------------------------------------------
extern "C" void kernel_launch(void* const* d_in, const int* in_sizes, int n_in,
                              void* d_out, int out_size) {
    const float* feat = (const float*)d_in[0];
    const float* W    = (const float*)d_in[1];
    const int*   src  = (const int*)d_in[2];
    const int*   dst  = (const int*)d_in[3];
    float* out = (float*)d_out;

    k_gemm <<<N_NODES / 16, 256>>>(feat, W, dst);   // 3125 blocks, fused hist
    k_alloc<<<NB, 256>>>();
    k_place<<<N_EDGES / 256, 256>>>(src, dst);      // 3125 blocks
    k_agg  <<<N_NODES * 16 / 256, 256>>>(out);      // 3125 blocks
}

// round 10
// speedup vs baseline: 1.9209x; 1.1480x over previous
#include <cuda_runtime.h>
#include <cuda_bf16.h>

#define N_NODES 50000
#define N_EDGES 800000
#define D_IN    128
#define HF      64
#define NB      196            // ceil(50000/256)
#define GB      782            // ceil(50000/64) nodes-per-block=64; also agg grid
#define GSTRIDE (GB * 256)
#define GEMM_SMEM (2 * 64 * 132 * 4)   // sWt[64][132] + sfeat[64][132] floats

// Static scratch (allocation is forbidden)
__device__ float g_ft[N_NODES * HF];
__device__ int   g_count[N_NODES];     // zero-init; k_alloc re-zeroes each replay
__device__ int   g_off[N_NODES];
__device__ int   g_cnt[N_NODES];
__device__ int   g_cursor[N_NODES];
__device__ int   g_srcs[N_EDGES];
__device__ int   g_total;

// Packed fp32x2 FMA (Blackwell FFMA2, PTX-only)
#define FMA2(acc, a, b) \
    asm("fma.rn.f32x2 %0, %1, %2, %0;" : "+l"(acc) : "l"(a), "l"(b))

__device__ __forceinline__ float hsum(unsigned long long v) {
    float a, b; asm("mov.b64 {%0,%1}, %2;" : "=f"(a), "=f"(b) : "l"(v));
    return a + b;
}
__device__ __forceinline__ unsigned long long fpack(float x) {
    unsigned long long v; asm("mov.b64 %0, {%1,%1};" : "=l"(v) : "f"(x));
    return v;
}
__device__ __forceinline__ void funpack(unsigned long long v, float& a, float& b) {
    asm("mov.b64 {%0,%1}, %2;" : "=f"(a), "=f"(b) : "l"(v));
}

// ---------------------------------------------------------------------------
// K1: ft = feat @ W  ([N,128]@[128,64]) with 4x4 register tiling.
// 64 nodes/block, 256 threads = 16 col-groups x 16 node-groups.
// Thread (cg,ng) computes cols {cg,cg+16,cg+32,cg+48} x nodes {4ng..4ng+3}.
// Both smem arrays padded to 132 floats/row (16B-aligned, bank-derotated).
// dst histogram fused via a 4-pass stride loop.
// ---------------------------------------------------------------------------
__global__ __launch_bounds__(256) void k_gemm(const float* __restrict__ feat,
                                              const float* __restrict__ W,
                                              const int* __restrict__ dst) {
    extern __shared__ float sm[];
    float* sWt = sm;                 // [64][132], Wt[c][k]
    float* sft = sm + 64 * 132;      // [64][132], feat rows (first 128 valid)

    int tid  = threadIdx.x;
    int gtid = blockIdx.x * 256 + tid;
    if (gtid == 0) g_total = 0;
    for (int e = gtid; e < N_EDGES; e += GSTRIDE)
        atomicAdd(&g_count[dst[e]], 1);

    for (int idx = tid; idx < D_IN * HF; idx += 256) {
        int k = idx >> 6, c = idx & 63;
        sWt[c * 132 + k] = W[idx];
    }
    int node0 = blockIdx.x * 64;
    const float4* fv = (const float4*)feat;
    float4* sf4 = (float4*)sft;                        // 33 float4 per row
    for (int idx = tid; idx < 64 * 32; idx += 256) {
        int r = idx >> 5, s = idx & 31;
        int n = node0 + r;
        sf4[r * 33 + s] = (n < N_NODES) ? fv[(size_t)n * 32 + s]
                                        : make_float4(0.f, 0.f, 0.f, 0.f);
    }
    __syncthreads();

    int cg = tid & 15, ng = tid >> 4;
    const ulonglong2* wb = (const ulonglong2*)sWt;     // 33 units / row
    const ulonglong2* ab = (const ulonglong2*)sft;
    int wo[4], ao[4];
    #pragma unroll
    for (int i = 0; i < 4; i++) wo[i] = (cg + 16 * i) * 33;
    #pragma unroll
    for (int r = 0; r < 4; r++) ao[r] = (4 * ng + r) * 33;

    unsigned long long acc[4][4];
    #pragma unroll
    for (int i = 0; i < 4; i++)
        #pragma unroll
        for (int r = 0; r < 4; r++) acc[i][r] = 0ull;

    #pragma unroll 2
    for (int k = 0; k < 32; k++) {                     // 32 chunks x 4 floats = K=128
        ulonglong2 w[4], a[4];
        #pragma unroll
        for (int i = 0; i < 4; i++) w[i] = wb[wo[i] + k];
        #pragma unroll
        for (int r = 0; r < 4; r++) a[r] = ab[ao[r] + k];
        #pragma unroll
        for (int i = 0; i < 4; i++)
            #pragma unroll
            for (int r = 0; r < 4; r++) {
                FMA2(acc[i][r], a[r].x, w[i].x);
                FMA2(acc[i][r], a[r].y, w[i].y);
            }
    }

    #pragma unroll
    for (int r = 0; r < 4; r++) {
        int n = node0 + 4 * ng + r;
        if (n < N_NODES) {
            #pragma unroll
            for (int i = 0; i < 4; i++)
                g_ft[(size_t)n * 64 + cg + 16 * i] = hsum(acc[i][r]);  // coalesced
        }
    }
}

// ---------------------------------------------------------------------------
// K2: segment allocation via global atomic cursor; re-zero g_count for replay.
// ---------------------------------------------------------------------------
__global__ void k_alloc() {
    int i = blockIdx.x * 256 + threadIdx.x;
    if (i < N_NODES) {
        int cnt = g_count[i];
        g_count[i] = 0;
        int off = atomicAdd(&g_total, cnt);
        g_off[i]    = off;
        g_cnt[i]    = cnt;
        g_cursor[i] = off;
    }
}

// ---------------------------------------------------------------------------
// K3: place src ids into per-dst segments (order within segment irrelevant)
// ---------------------------------------------------------------------------
__global__ void k_place(const int* __restrict__ src, const int* __restrict__ dst) {
    int e = blockIdx.x * 256 + threadIdx.x;            // exact: 3125*256
    int pos = atomicAdd(&g_cursor[dst[e]], 1);
    g_srcs[pos] = src[e];
}

// ---------------------------------------------------------------------------
// K4: fused score + softmax + aggregate. 4 lanes/node, lane = one full head
// (16 floats in registers). No shuffles; one exp per edge per head; packed
// f32x2 dot + weighted accumulation; x2 edge unroll for gather MLP.
// out[d] = (sum_e exp(e)*ft[src_e]) / sum_e exp(e)   (max-shift cancels)
// ---------------------------------------------------------------------------
__global__ __launch_bounds__(256) void k_agg(float* __restrict__ out) {
    int gtid = blockIdx.x * 256 + threadIdx.x;
    int node = gtid >> 2;
    if (node >= N_NODES) return;
    int h = gtid & 3;

    const ulonglong2* ftv = (const ulonglong2*)g_ft;   // 16B units, 16/row
    size_t bb = (size_t)node * 16 + h * 4;
    ulonglong2 b0 = ftv[bb], b1 = ftv[bb + 1], b2 = ftv[bb + 2], b3 = ftv[bb + 3];

    int beg = g_off[node], cnt = g_cnt[node];
    unsigned long long acc[8] = {0ull,0ull,0ull,0ull,0ull,0ull,0ull,0ull};
    float den = 0.f;

    int k = 0;
    for (; k + 2 <= cnt; k += 2) {
        int s0 = g_srcs[beg + k], s1 = g_srcs[beg + k + 1];
        size_t p0 = (size_t)s0 * 16 + h * 4;
        size_t p1 = (size_t)s1 * 16 + h * 4;
        ulonglong2 a0 = ftv[p0], a1 = ftv[p0+1], a2 = ftv[p0+2], a3 = ftv[p0+3];
        ulonglong2 c0 = ftv[p1], c1 = ftv[p1+1], c2 = ftv[p1+2], c3 = ftv[p1+3];

        unsigned long long d0 = 0ull, d1 = 0ull;
        FMA2(d0,a0.x,b0.x); FMA2(d0,a0.y,b0.y); FMA2(d0,a1.x,b1.x); FMA2(d0,a1.y,b1.y);
        FMA2(d0,a2.x,b2.x); FMA2(d0,a2.y,b2.y); FMA2(d0,a3.x,b3.x); FMA2(d0,a3.y,b3.y);
        FMA2(d1,c0.x,b0.x); FMA2(d1,c0.y,b0.y); FMA2(d1,c1.x,b1.x); FMA2(d1,c1.y,b1.y);
        FMA2(d1,c2.x,b2.x); FMA2(d1,c2.y,b2.y); FMA2(d1,c3.x,b3.x); FMA2(d1,c3.y,b3.y);

        float ex0 = __expf(hsum(d0) * 0.25f);
        float ex1 = __expf(hsum(d1) * 0.25f);
        unsigned long long e0 = fpack(ex0), e1 = fpack(ex1);

        FMA2(acc[0],a0.x,e0); FMA2(acc[1],a0.y,e0); FMA2(acc[2],a1.x,e0); FMA2(acc[3],a1.y,e0);
        FMA2(acc[4],a2.x,e0); FMA2(acc[5],a2.y,e0); FMA2(acc[6],a3.x,e0); FMA2(acc[7],a3.y,e0);
        FMA2(acc[0],c0.x,e1); FMA2(acc[1],c0.y,e1); FMA2(acc[2],c1.x,e1); FMA2(acc[3],c1.y,e1);
        FMA2(acc[4],c2.x,e1); FMA2(acc[5],c2.y,e1); FMA2(acc[6],c3.x,e1); FMA2(acc[7],c3.y,e1);
        den += ex0 + ex1;
    }
    if (k < cnt) {
        int s0 = g_srcs[beg + k];
        size_t p0 = (size_t)s0 * 16 + h * 4;
        ulonglong2 a0 = ftv[p0], a1 = ftv[p0+1], a2 = ftv[p0+2], a3 = ftv[p0+3];
        unsigned long long d0 = 0ull;
        FMA2(d0,a0.x,b0.x); FMA2(d0,a0.y,b0.y); FMA2(d0,a1.x,b1.x); FMA2(d0,a1.y,b1.y);
        FMA2(d0,a2.x,b2.x); FMA2(d0,a2.y,b2.y); FMA2(d0,a3.x,b3.x); FMA2(d0,a3.y,b3.y);
        float ex0 = __expf(hsum(d0) * 0.25f);
        unsigned long long e0 = fpack(ex0);
        FMA2(acc[0],a0.x,e0); FMA2(acc[1],a0.y,e0); FMA2(acc[2],a1.x,e0); FMA2(acc[3],a1.y,e0);
        FMA2(acc[4],a2.x,e0); FMA2(acc[5],a2.y,e0); FMA2(acc[6],a3.x,e0); FMA2(acc[7],a3.y,e0);
        den += ex0;
    }

    float inv = (den > 0.f) ? (1.f / den) : 0.f;       // isolated node -> zeros
    float4* ov = (float4*)out;
    size_t ob = (size_t)node * 16 + h * 4;
    #pragma unroll
    for (int v = 0; v < 4; v++) {
        float x, y, z, w;
        funpack(acc[2 * v],     x, y);
        funpack(acc[2 * v + 1], z, w);
        ov[ob + v] = make_float4(x * inv, y * inv, z * inv, w * inv);
    }
}

// ---------------------------------------------------------------------------
extern "C" void kernel_launch(void* const* d_in, const int* in_sizes, int n_in,
                              void* d_out, int out_size) {
    const float* feat = (const float*)d_in[0];
    const float* W    = (const float*)d_in[1];
    const int*   src  = (const int*)d_in[2];
    const int*   dst  = (const int*)d_in[3];
    float* out = (float*)d_out;

    cudaFuncSetAttribute(k_gemm, cudaFuncAttributeMaxDynamicSharedMemorySize,
                         GEMM_SMEM);
    k_gemm <<<GB, 256, GEMM_SMEM>>>(feat, W, dst);
    k_alloc<<<NB, 256>>>();
    k_place<<<N_EDGES / 256, 256>>>(src, dst);
    k_agg  <<<GB, 256>>>(out);
}

// round 12
// speedup vs baseline: 1.9267x; 1.0030x over previous
#include <cuda_runtime.h>
#include <cuda_bf16.h>

#define N_NODES 50000
#define N_EDGES 800000
#define D_IN    128
#define HF      64
#define NB      196            // ceil(50000/256)
#define GB      782            // ceil(50000/64) for gemm (64 nodes/block)
#define AGB     6250           // ceil(50000/8) for agg (8 warps/block, warp=node)
#define GSTRIDE (GB * 256)
#define GEMM_SMEM (2 * 64 * 132 * 4)

// Static scratch (allocation is forbidden)
__device__ float g_ft[N_NODES * HF];
__device__ int   g_count[N_NODES];     // zero-init; k_alloc re-zeroes each replay
__device__ int   g_off[N_NODES];
__device__ int   g_cnt[N_NODES];
__device__ int   g_cursor[N_NODES];
__device__ int   g_srcs[N_EDGES];
__device__ int   g_total;

// Packed fp32x2 FMA (Blackwell FFMA2, PTX-only)
#define FMA2(acc, a, b) \
    asm("fma.rn.f32x2 %0, %1, %2, %0;" : "+l"(acc) : "l"(a), "l"(b))

__device__ __forceinline__ float hsum(unsigned long long v) {
    float a, b; asm("mov.b64 {%0,%1}, %2;" : "=f"(a), "=f"(b) : "l"(v));
    return a + b;
}

// ---------------------------------------------------------------------------
// K1: ft = feat @ W ([N,128]@[128,64]), 4x4 register tile, 64 nodes/block,
// fused dst histogram (4-pass stride loop).
// ---------------------------------------------------------------------------
__global__ __launch_bounds__(256) void k_gemm(const float* __restrict__ feat,
                                              const float* __restrict__ W,
                                              const int* __restrict__ dst) {
    extern __shared__ float sm[];
    float* sWt = sm;                 // [64][132]
    float* sft = sm + 64 * 132;      // [64][132]

    int tid  = threadIdx.x;
    int gtid = blockIdx.x * 256 + tid;
    if (gtid == 0) g_total = 0;
    for (int e = gtid; e < N_EDGES; e += GSTRIDE)
        atomicAdd(&g_count[dst[e]], 1);

    for (int idx = tid; idx < D_IN * HF; idx += 256) {
        int k = idx >> 6, c = idx & 63;
        sWt[c * 132 + k] = W[idx];
    }
    int node0 = blockIdx.x * 64;
    const float4* fv = (const float4*)feat;
    float4* sf4 = (float4*)sft;
    for (int idx = tid; idx < 64 * 32; idx += 256) {
        int r = idx >> 5, s = idx & 31;
        int n = node0 + r;
        sf4[r * 33 + s] = (n < N_NODES) ? fv[(size_t)n * 32 + s]
                                        : make_float4(0.f, 0.f, 0.f, 0.f);
    }
    __syncthreads();

    int cg = tid & 15, ng = tid >> 4;
    const ulonglong2* wb = (const ulonglong2*)sWt;
    const ulonglong2* ab = (const ulonglong2*)sft;
    int wo[4], ao[4];
    #pragma unroll
    for (int i = 0; i < 4; i++) wo[i] = (cg + 16 * i) * 33;
    #pragma unroll
    for (int r = 0; r < 4; r++) ao[r] = (4 * ng + r) * 33;

    unsigned long long acc[4][4];
    #pragma unroll
    for (int i = 0; i < 4; i++)
        #pragma unroll
        for (int r = 0; r < 4; r++) acc[i][r] = 0ull;

    #pragma unroll 2
    for (int k = 0; k < 32; k++) {
        ulonglong2 w[4], a[4];
        #pragma unroll
        for (int i = 0; i < 4; i++) w[i] = wb[wo[i] + k];
        #pragma unroll
        for (int r = 0; r < 4; r++) a[r] = ab[ao[r] + k];
        #pragma unroll
        for (int i = 0; i < 4; i++)
            #pragma unroll
            for (int r = 0; r < 4; r++) {
                FMA2(acc[i][r], a[r].x, w[i].x);
                FMA2(acc[i][r], a[r].y, w[i].y);
            }
    }

    #pragma unroll
    for (int r = 0; r < 4; r++) {
        int n = node0 + 4 * ng + r;
        if (n < N_NODES) {
            #pragma unroll
            for (int i = 0; i < 4; i++)
                g_ft[(size_t)n * 64 + cg + 16 * i] = hsum(acc[i][r]);
        }
    }
}

// ---------------------------------------------------------------------------
// K2: segment allocation via global atomic cursor; re-zero g_count for replay.
// ---------------------------------------------------------------------------
__global__ void k_alloc() {
    int i = blockIdx.x * 256 + threadIdx.x;
    if (i < N_NODES) {
        int cnt = g_count[i];
        g_count[i] = 0;
        int off = atomicAdd(&g_total, cnt);
        g_off[i]    = off;
        g_cnt[i]    = cnt;
        g_cursor[i] = off;
    }
}

// ---------------------------------------------------------------------------
// K3: place src ids into per-dst segments
// ---------------------------------------------------------------------------
__global__ void k_place(const int* __restrict__ src, const int* __restrict__ dst) {
    int e = blockIdx.x * 256 + threadIdx.x;            // exact: 3125*256
    int pos = atomicAdd(&g_cursor[dst[e]], 1);
    g_srcs[pos] = src[e];
}

// ---------------------------------------------------------------------------
// K4: fused score + softmax + aggregate. ONE WARP PER NODE.
// 32 lanes = 2 edges x 16 lanes; lane j owns float4 #j of the 256B row
// (minimal 2 L1-lines/edge). Zero inter-node divergence. Indices prefetched
// 32-wide, broadcast by shfl. Head dot via shfl_xor(1),(2) within 4-lane
// head groups; edge pairs unrolled x2 (4 gathers in flight).
// out[d] = (sum_e exp(e)*ft[src_e]) / sum_e exp(e)   (max-shift cancels)
// ---------------------------------------------------------------------------
__global__ __launch_bounds__(256) void k_agg(float* __restrict__ out) {
    const unsigned FULL = 0xffffffffu;
    int warp = (blockIdx.x * 256 + threadIdx.x) >> 5;  // node id
    if (warp >= N_NODES) return;
    int lane = threadIdx.x & 31;
    int j    = lane & 15;          // float4 slot within row
    int e    = lane >> 4;          // edge slot 0/1

    const float4* ftv = (const float4*)g_ft;
    float4 b = ftv[(size_t)warp * 16 + j];             // broadcast across halves

    int beg = g_off[warp], cnt = g_cnt[warp];
    float4 acc = make_float4(0.f, 0.f, 0.f, 0.f);
    float den = 0.f;

#define EDGE(A, V) do {                                               \
        float p = (A).x * b.x + (A).y * b.y + (A).z * b.z + (A).w * b.w; \
        p += __shfl_xor_sync(FULL, p, 1);                             \
        p += __shfl_xor_sync(FULL, p, 2);                             \
        float ex = (V) ? __expf(p * 0.25f) : 0.f;                     \
        acc.x += ex * (A).x; acc.y += ex * (A).y;                     \
        acc.z += ex * (A).z; acc.w += ex * (A).w;                     \
        den += ex;                                                    \
    } while (0)

    for (int k0 = 0; k0 < cnt; k0 += 32) {
        int lim = cnt - k0; if (lim > 32) lim = 32;
        int myidx = (lane < lim) ? g_srcs[beg + k0 + lane] : 0;  // coalesced 128B
        int npair = (lim + 1) >> 1;

        int t = 0;
        for (; t + 2 <= npair; t += 2) {
            int ei0 = 2 * t + e, ei1 = 2 * t + 2 + e;
            int s0 = __shfl_sync(FULL, myidx, ei0);
            int s1 = __shfl_sync(FULL, myidx, ei1);
            float4 a0 = ftv[(size_t)s0 * 16 + j];      // 2 independent gathers
            float4 a1 = ftv[(size_t)s1 * 16 + j];
            EDGE(a0, ei0 < lim);
            EDGE(a1, ei1 < lim);
        }
        if (t < npair) {
            int ei0 = 2 * t + e;
            int s0 = __shfl_sync(FULL, myidx, ei0);
            float4 a0 = ftv[(size_t)s0 * 16 + j];
            EDGE(a0, ei0 < lim);
        }
    }
#undef EDGE

    // combine the two 16-lane halves (same j in both halves)
    acc.x += __shfl_xor_sync(FULL, acc.x, 16);
    acc.y += __shfl_xor_sync(FULL, acc.y, 16);
    acc.z += __shfl_xor_sync(FULL, acc.z, 16);
    acc.w += __shfl_xor_sync(FULL, acc.w, 16);
    den   += __shfl_xor_sync(FULL, den,   16);

    if (lane < 16) {
        float inv = (den > 0.f) ? (1.f / den) : 0.f;   // isolated node -> zeros
        ((float4*)out)[(size_t)warp * 16 + j] =
            make_float4(acc.x * inv, acc.y * inv, acc.z * inv, acc.w * inv);
    }
}

// ---------------------------------------------------------------------------
extern "C" void kernel_launch(void* const* d_in, const int* in_sizes, int n_in,
                              void* d_out, int out_size) {
    const float* feat = (const float*)d_in[0];
    const float* W    = (const float*)d_in[1];
    const int*   src  = (const int*)d_in[2];
    const int*   dst  = (const int*)d_in[3];
    float* out = (float*)d_out;

    cudaFuncSetAttribute(k_gemm, cudaFuncAttributeMaxDynamicSharedMemorySize,
                         GEMM_SMEM);
    k_gemm <<<GB, 256, GEMM_SMEM>>>(feat, W, dst);
    k_alloc<<<NB, 256>>>();
    k_place<<<N_EDGES / 256, 256>>>(src, dst);
    k_agg  <<<AGB, 256>>>(out);
}

// round 13
// speedup vs baseline: 2.1288x; 1.1049x over previous
#include <cuda_runtime.h>
#include <cuda_bf16.h>

#define N_NODES 50000
#define N_EDGES 800000
#define D_IN    128
#define HF      64
#define NB      196            // ceil(50000/256)
#define GB      782            // ceil(50000/64) for gemm (64 nodes/block)
#define AGB     6250           // ceil(50000/8) for agg (8 warps/block, warp=node)
#define GSTRIDE (GB * 256)
#define GEMM_SMEM (2 * 64 * 132 * 4)

// Static scratch (allocation is forbidden)
__device__ float g_ft[N_NODES * HF];
__device__ int   g_count[N_NODES];     // zero-init; k_alloc re-zeroes each replay
__device__ int   g_off[N_NODES];
__device__ int   g_cnt[N_NODES];
__device__ int   g_cursor[N_NODES];
__device__ int   g_srcs[N_EDGES];
__device__ int   g_total;

// Packed fp32x2 FMA (Blackwell FFMA2, PTX-only)
#define FMA2(acc, a, b) \
    asm("fma.rn.f32x2 %0, %1, %2, %0;" : "+l"(acc) : "l"(a), "l"(b))

__device__ __forceinline__ float hsum(unsigned long long v) {
    float a, b; asm("mov.b64 {%0,%1}, %2;" : "=f"(a), "=f"(b) : "l"(v));
    return a + b;
}

// ---------------------------------------------------------------------------
// K1: ft = feat @ W ([N,128]@[128,64]), 4x4 register tile, 64 nodes/block,
// fused dst histogram (4-pass stride loop).
// ---------------------------------------------------------------------------
__global__ __launch_bounds__(256) void k_gemm(const float* __restrict__ feat,
                                              const float* __restrict__ W,
                                              const int* __restrict__ dst) {
    extern __shared__ float sm[];
    float* sWt = sm;                 // [64][132]
    float* sft = sm + 64 * 132;      // [64][132]

    int tid  = threadIdx.x;
    int gtid = blockIdx.x * 256 + tid;
    if (gtid == 0) g_total = 0;
    for (int e = gtid; e < N_EDGES; e += GSTRIDE)
        atomicAdd(&g_count[dst[e]], 1);

    for (int idx = tid; idx < D_IN * HF; idx += 256) {
        int k = idx >> 6, c = idx & 63;
        sWt[c * 132 + k] = W[idx];
    }
    int node0 = blockIdx.x * 64;
    const float4* fv = (const float4*)feat;
    float4* sf4 = (float4*)sft;
    for (int idx = tid; idx < 64 * 32; idx += 256) {
        int r = idx >> 5, s = idx & 31;
        int n = node0 + r;
        sf4[r * 33 + s] = (n < N_NODES) ? fv[(size_t)n * 32 + s]
                                        : make_float4(0.f, 0.f, 0.f, 0.f);
    }
    __syncthreads();

    int cg = tid & 15, ng = tid >> 4;
    const ulonglong2* wb = (const ulonglong2*)sWt;
    const ulonglong2* ab = (const ulonglong2*)sft;
    int wo[4], ao[4];
    #pragma unroll
    for (int i = 0; i < 4; i++) wo[i] = (cg + 16 * i) * 33;
    #pragma unroll
    for (int r = 0; r < 4; r++) ao[r] = (4 * ng + r) * 33;

    unsigned long long acc[4][4];
    #pragma unroll
    for (int i = 0; i < 4; i++)
        #pragma unroll
        for (int r = 0; r < 4; r++) acc[i][r] = 0ull;

    #pragma unroll 2
    for (int k = 0; k < 32; k++) {
        ulonglong2 w[4], a[4];
        #pragma unroll
        for (int i = 0; i < 4; i++) w[i] = wb[wo[i] + k];
        #pragma unroll
        for (int r = 0; r < 4; r++) a[r] = ab[ao[r] + k];
        #pragma unroll
        for (int i = 0; i < 4; i++)
            #pragma unroll
            for (int r = 0; r < 4; r++) {
                FMA2(acc[i][r], a[r].x, w[i].x);
                FMA2(acc[i][r], a[r].y, w[i].y);
            }
    }

    #pragma unroll
    for (int r = 0; r < 4; r++) {
        int n = node0 + 4 * ng + r;
        if (n < N_NODES) {
            #pragma unroll
            for (int i = 0; i < 4; i++)
                g_ft[(size_t)n * 64 + cg + 16 * i] = hsum(acc[i][r]);
        }
    }
}

// ---------------------------------------------------------------------------
// K2: segment allocation via global atomic cursor; re-zero g_count for replay.
// ---------------------------------------------------------------------------
__global__ void k_alloc() {
    int i = blockIdx.x * 256 + threadIdx.x;
    if (i < N_NODES) {
        int cnt = g_count[i];
        g_count[i] = 0;
        int off = atomicAdd(&g_total, cnt);
        g_off[i]    = off;
        g_cnt[i]    = cnt;
        g_cursor[i] = off;
    }
}

// ---------------------------------------------------------------------------
// K3: place src ids into per-dst segments
// ---------------------------------------------------------------------------
__global__ void k_place(const int* __restrict__ src, const int* __restrict__ dst) {
    int e = blockIdx.x * 256 + threadIdx.x;            // exact: 3125*256
    int pos = atomicAdd(&g_cursor[dst[e]], 1);
    g_srcs[pos] = src[e];
}

// ---------------------------------------------------------------------------
// K4: fused score + softmax + aggregate. ONE WARP PER NODE.
// 32 lanes = 2 edges x 16 lanes; lane j owns float4 #j (2 L1 lines/edge, the
// floor). All addressing 32-bit. Full-pair fast path is UNPREDICATED; single
// odd edge peeled. x4 unroll = 4 independent gathers in flight per lane.
// out[d] = (sum_e exp(e)*ft[src_e]) / sum_e exp(e)   (max-shift cancels)
// ---------------------------------------------------------------------------
__global__ __launch_bounds__(256) void k_agg(float* __restrict__ out) {
    const unsigned FULL = 0xffffffffu;
    int warp = (blockIdx.x * 256 + threadIdx.x) >> 5;  // node id
    if (warp >= N_NODES) return;
    int lane = threadIdx.x & 31;
    int j    = lane & 15;          // float4 slot within 256B row
    int e    = lane >> 4;          // edge slot 0/1

    const float4* __restrict__ ftv = (const float4*)g_ft;
    float4 b = ftv[warp * 16 + j];                     // 32-bit index

    int beg = g_off[warp], cnt = g_cnt[warp];
    float4 acc = make_float4(0.f, 0.f, 0.f, 0.f);
    float den = 0.f;

#define EDGEF(A) do {                                                 \
        float p = (A).x * b.x + (A).y * b.y + (A).z * b.z + (A).w * b.w; \
        p += __shfl_xor_sync(FULL, p, 1);                             \
        p += __shfl_xor_sync(FULL, p, 2);                             \
        float ex = __expf(p * 0.25f);                                 \
        acc.x += ex * (A).x; acc.y += ex * (A).y;                     \
        acc.z += ex * (A).z; acc.w += ex * (A).w;                     \
        den += ex;                                                    \
    } while (0)

    for (int k0 = 0; k0 < cnt; k0 += 32) {
        int lim = cnt - k0; if (lim > 32) lim = 32;
        int myidx = (lane < lim) ? g_srcs[beg + k0 + lane] : 0;  // coalesced
        int npair = lim >> 1;                          // full pairs only

        int t = 0;
        for (; t + 4 <= npair; t += 4) {               // 8 edges, 4 loads in flight
            int s0 = __shfl_sync(FULL, myidx, 2 * t + e);
            int s1 = __shfl_sync(FULL, myidx, 2 * t + 2 + e);
            int s2 = __shfl_sync(FULL, myidx, 2 * t + 4 + e);
            int s3 = __shfl_sync(FULL, myidx, 2 * t + 6 + e);
            float4 a0 = ftv[s0 * 16 + j];
            float4 a1 = ftv[s1 * 16 + j];
            float4 a2 = ftv[s2 * 16 + j];
            float4 a3 = ftv[s3 * 16 + j];
            EDGEF(a0); EDGEF(a1); EDGEF(a2); EDGEF(a3);
        }
        for (; t < npair; ++t) {
            int s0 = __shfl_sync(FULL, myidx, 2 * t + e);
            float4 a0 = ftv[s0 * 16 + j];
            EDGEF(a0);
        }
        if (lim & 1) {                                 // peeled odd edge
            int s0 = __shfl_sync(FULL, myidx, lim - 1);
            float4 a0 = ftv[s0 * 16 + j];
            float p = a0.x * b.x + a0.y * b.y + a0.z * b.z + a0.w * b.w;
            p += __shfl_xor_sync(FULL, p, 1);
            p += __shfl_xor_sync(FULL, p, 2);
            float ex = (e == 0) ? __expf(p * 0.25f) : 0.f;  // count once
            acc.x += ex * a0.x; acc.y += ex * a0.y;
            acc.z += ex * a0.z; acc.w += ex * a0.w;
            den += ex;
        }
    }
#undef EDGEF

    // combine the two 16-lane halves (same j in both halves)
    acc.x += __shfl_xor_sync(FULL, acc.x, 16);
    acc.y += __shfl_xor_sync(FULL, acc.y, 16);
    acc.z += __shfl_xor_sync(FULL, acc.z, 16);
    acc.w += __shfl_xor_sync(FULL, acc.w, 16);
    den   += __shfl_xor_sync(FULL, den,   16);

    if (lane < 16) {
        float inv = (den > 0.f) ? (1.f / den) : 0.f;   // isolated node -> zeros
        ((float4*)out)[warp * 16 + j] =
            make_float4(acc.x * inv, acc.y * inv, acc.z * inv, acc.w * inv);
    }
}

// ---------------------------------------------------------------------------
extern "C" void kernel_launch(void* const* d_in, const int* in_sizes, int n_in,
                              void* d_out, int out_size) {
    const float* feat = (const float*)d_in[0];
    const float* W    = (const float*)d_in[1];
    const int*   src  = (const int*)d_in[2];
    const int*   dst  = (const int*)d_in[3];
    float* out = (float*)d_out;

    cudaFuncSetAttribute(k_gemm, cudaFuncAttributeMaxDynamicSharedMemorySize,
                         GEMM_SMEM);
    k_gemm <<<GB, 256, GEMM_SMEM>>>(feat, W, dst);
    k_alloc<<<NB, 256>>>();
    k_place<<<N_EDGES / 256, 256>>>(src, dst);
    k_agg  <<<AGB, 256>>>(out);
}